// round 1
// baseline (speedup 1.0000x reference)
#include <cuda_runtime.h>
#include <math.h>

#define D_MODEL 1024
#define NHEAD   16
#define D_HEAD  64
#define BATCH   4
#define T_SEQ   2048
#define BT      (BATCH * T_SEQ)   // 8192

// Scratch buffers (allocation-free rule: __device__ globals)
__device__ float g_Q[BT * D_MODEL];
__device__ float g_K[BT * D_MODEL];
__device__ float g_V[BT * D_MODEL];
__device__ float g_O[BT * D_MODEL];

// ---------------------------------------------------------------------------
// GEMM core: C[M,N] = A[M,K] @ W[N,K]^T + bias, optional fused RoPE epilogue.
// 128x128 block tile, BK=16, 256 threads, 8x8 per thread.
// ---------------------------------------------------------------------------
__device__ __forceinline__ void gemm_core(const float* __restrict__ A,
                                          const float* __restrict__ W,
                                          const float* __restrict__ bias,
                                          float* __restrict__ C,
                                          bool rope)
{
    __shared__ float As[16][128];   // [k][m]
    __shared__ float Bs[16][128];   // [k][n]

    const int tid = threadIdx.x;
    const int ty = tid >> 4;        // 0..15
    const int tx = tid & 15;        // 0..15
    const int bm = blockIdx.y * 128;
    const int bn = blockIdx.x * 128;

    float acc[8][8];
#pragma unroll
    for (int i = 0; i < 8; i++)
#pragma unroll
        for (int j = 0; j < 8; j++) acc[i][j] = 0.f;

    const int lr = tid >> 1;          // 0..127
    const int lc = (tid & 1) * 8;     // 0 or 8
    const float* Aptr = A + (size_t)(bm + lr) * D_MODEL + lc;
    const float* Wptr = W + (size_t)(bn + lr) * D_MODEL + lc;

    for (int kt = 0; kt < D_MODEL; kt += 16) {
        float4 a0 = *(const float4*)(Aptr + kt);
        float4 a1 = *(const float4*)(Aptr + kt + 4);
        float4 w0 = *(const float4*)(Wptr + kt);
        float4 w1 = *(const float4*)(Wptr + kt + 4);
        __syncthreads();
        As[lc + 0][lr] = a0.x; As[lc + 1][lr] = a0.y;
        As[lc + 2][lr] = a0.z; As[lc + 3][lr] = a0.w;
        As[lc + 4][lr] = a1.x; As[lc + 5][lr] = a1.y;
        As[lc + 6][lr] = a1.z; As[lc + 7][lr] = a1.w;
        Bs[lc + 0][lr] = w0.x; Bs[lc + 1][lr] = w0.y;
        Bs[lc + 2][lr] = w0.z; Bs[lc + 3][lr] = w0.w;
        Bs[lc + 4][lr] = w1.x; Bs[lc + 5][lr] = w1.y;
        Bs[lc + 6][lr] = w1.z; Bs[lc + 7][lr] = w1.w;
        __syncthreads();
#pragma unroll
        for (int k = 0; k < 16; k++) {
            float4 af0 = *(const float4*)&As[k][ty * 8];
            float4 af1 = *(const float4*)&As[k][ty * 8 + 4];
            float4 bf0 = *(const float4*)&Bs[k][tx * 8];
            float4 bf1 = *(const float4*)&Bs[k][tx * 8 + 4];
            float a[8] = {af0.x, af0.y, af0.z, af0.w, af1.x, af1.y, af1.z, af1.w};
            float b[8] = {bf0.x, bf0.y, bf0.z, bf0.w, bf1.x, bf1.y, bf1.z, bf1.w};
#pragma unroll
            for (int i = 0; i < 8; i++)
#pragma unroll
                for (int j = 0; j < 8; j++) acc[i][j] = fmaf(a[i], b[j], acc[i][j]);
        }
    }

    const int mbase = bm + ty * 8;
    const int nbase = bn + tx * 8;
    if (rope) {
#pragma unroll
        for (int i = 0; i < 8; i++) {
            int m = mbase + i;
            float tpos = (float)(m & (T_SEQ - 1));
#pragma unroll
            for (int j = 0; j < 8; j += 2) {
                int n = nbase + j;
                float v0 = acc[i][j]     + bias[n];
                float v1 = acc[i][j + 1] + bias[n + 1];
                int d = n & (D_HEAD - 1);
                float ang = tpos * ((float)(d >> 1) * 1e-4f);
                float sa, ca;
                sincosf(ang, &sa, &ca);
                C[(size_t)m * D_MODEL + n]     = v0 * ca - v1 * sa;
                C[(size_t)m * D_MODEL + n + 1] = v0 * sa + v1 * ca;
            }
        }
    } else {
#pragma unroll
        for (int i = 0; i < 8; i++) {
            int m = mbase + i;
#pragma unroll
            for (int j = 0; j < 8; j++) {
                int n = nbase + j;
                C[(size_t)m * D_MODEL + n] = acc[i][j] + bias[n];
            }
        }
    }
}

__global__ void __launch_bounds__(256)
qkv_gemm_kernel(const float* __restrict__ x,
                const float* __restrict__ Wq, const float* __restrict__ bq,
                const float* __restrict__ Wk, const float* __restrict__ bk,
                const float* __restrict__ Wv, const float* __restrict__ bv)
{
    int z = blockIdx.z;
    const float* W    = (z == 0) ? Wq : (z == 1) ? Wk : Wv;
    const float* bias = (z == 0) ? bq : (z == 1) ? bk : bv;
    float* C          = (z == 0) ? g_Q : (z == 1) ? g_K : g_V;
    gemm_core(x, W, bias, C, z < 2);
}

__global__ void __launch_bounds__(256)
out_gemm_kernel(const float* __restrict__ Wo, const float* __restrict__ bo,
                float* __restrict__ out)
{
    gemm_core(g_O, Wo, bo, out, false);
}

// ---------------------------------------------------------------------------
// Flash attention: one block per (64-query tile, b*h). 256 threads.
// Streams 64-key K/V tiles with online softmax. All fp32.
// smem layouts (pitch AP=68 floats, 16B-friendly):
//   Qs [d][m], Ks [d][n]  (transposed -> outer-product S compute)
//   Vs [k][d], Ps [k][m]
// ---------------------------------------------------------------------------
#define AP 68

__global__ void __launch_bounds__(256)
attn_kernel()
{
    extern __shared__ float sm[];
    float* Qs = sm;
    float* Ks = sm + 64 * AP;
    float* Vs = sm + 2 * 64 * AP;
    float* Ps = sm + 3 * 64 * AP;

    const int tid = threadIdx.x;
    const int ty = tid >> 4;    // 0..15 -> rows ty*4..+3
    const int tx = tid & 15;    // 0..15 -> cols tx*4..+3
    const int qt = blockIdx.x;  // 0..31
    const int bh = blockIdx.y;  // 0..63
    const int b = bh >> 4;
    const int h = bh & 15;

    const float* Qg = g_Q + (size_t)(b * T_SEQ + qt * 64) * D_MODEL + h * D_HEAD;
    const float* Kg = g_K + (size_t)(b * T_SEQ) * D_MODEL + h * D_HEAD;
    const float* Vg = g_V + (size_t)(b * T_SEQ) * D_MODEL + h * D_HEAD;

    // Load Q tile transposed: Qs[d][m]
    {
        int r = tid >> 2;              // 0..63 (query row)
        int c0 = (tid & 3) * 16;       // 0,16,32,48
        const float* src = Qg + (size_t)r * D_MODEL + c0;
#pragma unroll
        for (int u = 0; u < 16; u += 4) {
            float4 v = *(const float4*)(src + u);
            Qs[(c0 + u + 0) * AP + r] = v.x;
            Qs[(c0 + u + 1) * AP + r] = v.y;
            Qs[(c0 + u + 2) * AP + r] = v.z;
            Qs[(c0 + u + 3) * AP + r] = v.w;
        }
    }

    float m_i[4], l_i[4], o[4][4];
#pragma unroll
    for (int i = 0; i < 4; i++) {
        m_i[i] = -1e30f;
        l_i[i] = 0.f;
#pragma unroll
        for (int j = 0; j < 4; j++) o[i][j] = 0.f;
    }

    for (int kt = 0; kt < T_SEQ / 64; kt++) {
        __syncthreads();  // protect Ks/Vs/Ps reads from previous iteration
        // Load K (transposed) and V (natural) tiles
        {
            int r = tid >> 2;
            int c0 = (tid & 3) * 16;
            const float* ks = Kg + (size_t)(kt * 64 + r) * D_MODEL + c0;
            const float* vs = Vg + (size_t)(kt * 64 + r) * D_MODEL + c0;
#pragma unroll
            for (int u = 0; u < 16; u += 4) {
                float4 kv = *(const float4*)(ks + u);
                Ks[(c0 + u + 0) * AP + r] = kv.x;
                Ks[(c0 + u + 1) * AP + r] = kv.y;
                Ks[(c0 + u + 2) * AP + r] = kv.z;
                Ks[(c0 + u + 3) * AP + r] = kv.w;
                float4 vv = *(const float4*)(vs + u);
                *(float4*)&Vs[r * AP + c0 + u] = vv;
            }
        }
        __syncthreads();

        // S = (Q K^T) / sqrt(Dh)
        float s[4][4];
#pragma unroll
        for (int i = 0; i < 4; i++)
#pragma unroll
            for (int j = 0; j < 4; j++) s[i][j] = 0.f;
#pragma unroll
        for (int d = 0; d < 64; d++) {
            float4 q4 = *(const float4*)&Qs[d * AP + ty * 4];
            float4 k4 = *(const float4*)&Ks[d * AP + tx * 4];
            float qv[4] = {q4.x, q4.y, q4.z, q4.w};
            float kv[4] = {k4.x, k4.y, k4.z, k4.w};
#pragma unroll
            for (int i = 0; i < 4; i++)
#pragma unroll
                for (int j = 0; j < 4; j++) s[i][j] = fmaf(qv[i], kv[j], s[i][j]);
        }
#pragma unroll
        for (int i = 0; i < 4; i++)
#pragma unroll
            for (int j = 0; j < 4; j++) s[i][j] *= 0.125f;

        // Online softmax (row state replicated across the 16 tx lanes)
#pragma unroll
        for (int i = 0; i < 4; i++) {
            float mx = fmaxf(fmaxf(s[i][0], s[i][1]), fmaxf(s[i][2], s[i][3]));
#pragma unroll
            for (int off = 1; off < 16; off <<= 1)
                mx = fmaxf(mx, __shfl_xor_sync(0xffffffffu, mx, off));
            float mn = fmaxf(m_i[i], mx);
            float corr = expf(m_i[i] - mn);
            m_i[i] = mn;
            float rs = 0.f;
#pragma unroll
            for (int j = 0; j < 4; j++) {
                s[i][j] = expf(s[i][j] - mn);
                rs += s[i][j];
            }
#pragma unroll
            for (int off = 1; off < 16; off <<= 1)
                rs += __shfl_xor_sync(0xffffffffu, rs, off);
            l_i[i] = l_i[i] * corr + rs;
#pragma unroll
            for (int j = 0; j < 4; j++) o[i][j] *= corr;
        }

        // Write P transposed: Ps[k][m]
#pragma unroll
        for (int i = 0; i < 4; i++)
#pragma unroll
            for (int j = 0; j < 4; j++)
                Ps[(tx * 4 + j) * AP + ty * 4 + i] = s[i][j];
        __syncthreads();

        // O += P V
#pragma unroll
        for (int k = 0; k < 64; k++) {
            float4 p4 = *(const float4*)&Ps[k * AP + ty * 4];
            float4 v4 = *(const float4*)&Vs[k * AP + tx * 4];
            float pv[4] = {p4.x, p4.y, p4.z, p4.w};
            float vv[4] = {v4.x, v4.y, v4.z, v4.w};
#pragma unroll
            for (int i = 0; i < 4; i++)
#pragma unroll
                for (int j = 0; j < 4; j++) o[i][j] = fmaf(pv[i], vv[j], o[i][j]);
        }
    }

    // Finalize and store to [B,T,H*Dh]
#pragma unroll
    for (int i = 0; i < 4; i++) {
        float inv = 1.f / l_i[i];
        int m = b * T_SEQ + qt * 64 + ty * 4 + i;
#pragma unroll
        for (int j = 0; j < 4; j++)
            g_O[(size_t)m * D_MODEL + h * D_HEAD + tx * 4 + j] = o[i][j] * inv;
    }
}

// ---------------------------------------------------------------------------
extern "C" void kernel_launch(void* const* d_in, const int* in_sizes, int n_in,
                              void* d_out, int out_size)
{
    const float* x  = (const float*)d_in[0];
    const float* Wq = (const float*)d_in[1];
    const float* bq = (const float*)d_in[2];
    const float* Wk = (const float*)d_in[3];
    const float* bk = (const float*)d_in[4];
    const float* Wv = (const float*)d_in[5];
    const float* bv = (const float*)d_in[6];
    const float* Wo = (const float*)d_in[7];
    const float* bo = (const float*)d_in[8];
    float* out = (float*)d_out;

    static bool attr_set = false;
    if (!attr_set) {
        cudaFuncSetAttribute(attn_kernel,
                             cudaFuncAttributeMaxDynamicSharedMemorySize,
                             4 * 64 * AP * sizeof(float));
        attr_set = true;
    }

    dim3 gq(D_MODEL / 128, BT / 128, 3);
    qkv_gemm_kernel<<<gq, 256>>>(x, Wq, bq, Wk, bk, Wv, bv);

    dim3 ga(T_SEQ / 64, BATCH * NHEAD);
    attn_kernel<<<ga, 256, 4 * 64 * AP * sizeof(float)>>>();

    dim3 go(D_MODEL / 128, BT / 128, 1);
    out_gemm_kernel<<<go, 256>>>(Wo, bo, out);
}

// round 2
// speedup vs baseline: 2.6557x; 2.6557x over previous
#include <cuda_runtime.h>
#include <math.h>

#define D_MODEL 1024
#define NHEAD   16
#define D_HEAD  64
#define BATCH   4
#define T_SEQ   2048
#define BT      (BATCH * T_SEQ)   // 8192

__device__ float g_Q[BT * D_MODEL];
__device__ float g_K[BT * D_MODEL];
__device__ float g_V[BT * D_MODEL];
__device__ float g_O[BT * D_MODEL];

// ---------------------------------------------------------------------------
// helpers
// ---------------------------------------------------------------------------
__device__ __forceinline__ unsigned f2tf(float f) {
    unsigned u;
    asm("cvt.rna.tf32.f32 %0, %1;" : "=r"(u) : "f"(f));
    return u;
}

__device__ __forceinline__ void mma_tf32(float* c, const unsigned* a, const unsigned* b) {
    asm volatile(
        "mma.sync.aligned.m16n8k8.row.col.f32.tf32.tf32.f32 "
        "{%0,%1,%2,%3}, {%4,%5,%6,%7}, {%8,%9}, {%0,%1,%2,%3};"
        : "+f"(c[0]), "+f"(c[1]), "+f"(c[2]), "+f"(c[3])
        : "r"(a[0]), "r"(a[1]), "r"(a[2]), "r"(a[3]), "r"(b[0]), "r"(b[1]));
}

// ---------------------------------------------------------------------------
// tf32 GEMM: C[M,N] = A[M,K] @ W[N,K]^T + bias (+ fused RoPE)
// 128x128 block, BK=32, 256 threads, 8 warps (2M x 4N), warp tile 64x32.
// smem [k][m] pitch 136 -> conflict-free fragment loads.
// ---------------------------------------------------------------------------
#define GP 136

__device__ __forceinline__ void gemm_tf32_core(const float* __restrict__ A,
                                               const float* __restrict__ W,
                                               const float* __restrict__ bias,
                                               float* __restrict__ C,
                                               bool rope)
{
    __shared__ unsigned As[32][GP];
    __shared__ unsigned Bs[32][GP];

    const int tid  = threadIdx.x;
    const int lane = tid & 31;
    const int wid  = tid >> 5;
    const int g = lane >> 2;    // groupID 0..7
    const int t = lane & 3;     // tid in group 0..3
    const int wm = (wid & 1) * 64;
    const int wn = (wid >> 1) * 32;
    const int bm = blockIdx.y * 128;
    const int bn = blockIdx.x * 128;

    float acc[4][4][4];
#pragma unroll
    for (int mf = 0; mf < 4; mf++)
#pragma unroll
        for (int nf = 0; nf < 4; nf++)
#pragma unroll
            for (int i = 0; i < 4; i++) acc[mf][nf][i] = 0.f;

    const int lr = tid >> 1;          // 0..127
    const int lk = (tid & 1) * 16;    // 0 or 16
    const float* Ap = A + (size_t)(bm + lr) * D_MODEL + lk;
    const float* Wp = W + (size_t)(bn + lr) * D_MODEL + lk;

    for (int kt = 0; kt < D_MODEL; kt += 32) {
        float4 av[4], wv[4];
#pragma unroll
        for (int u = 0; u < 4; u++) {
            av[u] = *(const float4*)(Ap + kt + 4 * u);
            wv[u] = *(const float4*)(Wp + kt + 4 * u);
        }
        __syncthreads();
#pragma unroll
        for (int u = 0; u < 4; u++) {
            As[lk + 4 * u + 0][lr] = f2tf(av[u].x);
            As[lk + 4 * u + 1][lr] = f2tf(av[u].y);
            As[lk + 4 * u + 2][lr] = f2tf(av[u].z);
            As[lk + 4 * u + 3][lr] = f2tf(av[u].w);
            Bs[lk + 4 * u + 0][lr] = f2tf(wv[u].x);
            Bs[lk + 4 * u + 1][lr] = f2tf(wv[u].y);
            Bs[lk + 4 * u + 2][lr] = f2tf(wv[u].z);
            Bs[lk + 4 * u + 3][lr] = f2tf(wv[u].w);
        }
        __syncthreads();

#pragma unroll
        for (int kf = 0; kf < 4; kf++) {
            const int kr = kf * 8 + t;
            unsigned a[4][4], b[4][2];
#pragma unroll
            for (int mf = 0; mf < 4; mf++) {
                const int m = wm + mf * 16 + g;
                a[mf][0] = As[kr][m];
                a[mf][1] = As[kr][m + 8];
                a[mf][2] = As[kr + 4][m];
                a[mf][3] = As[kr + 4][m + 8];
            }
#pragma unroll
            for (int nf = 0; nf < 4; nf++) {
                const int n = wn + nf * 8 + g;
                b[nf][0] = Bs[kr][n];
                b[nf][1] = Bs[kr + 4][n];
            }
#pragma unroll
            for (int mf = 0; mf < 4; mf++)
#pragma unroll
                for (int nf = 0; nf < 4; nf++)
                    mma_tf32(acc[mf][nf], a[mf], b[nf]);
        }
    }

    // Epilogue: bias (+ RoPE). C fragment: c0/c1 = row g, cols 2t/2t+1; c2/c3 = row g+8.
#pragma unroll
    for (int mf = 0; mf < 4; mf++) {
        const int r0 = bm + wm + mf * 16 + g;
        const int r1 = r0 + 8;
#pragma unroll
        for (int nf = 0; nf < 4; nf++) {
            const int col = bn + wn + nf * 8 + 2 * t;   // even
            const float b0 = bias[col];
            const float b1 = bias[col + 1];
            float c0 = acc[mf][nf][0] + b0;
            float c1 = acc[mf][nf][1] + b1;
            float c2 = acc[mf][nf][2] + b0;
            float c3 = acc[mf][nf][3] + b1;
            if (rope) {
                const int d = col & (D_HEAD - 1);
                const float fr = (float)(d >> 1) * 1e-4f;
                float sa, ca;
                __sincosf((float)(r0 & (T_SEQ - 1)) * fr, &sa, &ca);
                float o0 = c0 * ca - c1 * sa;
                float o1 = c0 * sa + c1 * ca;
                c0 = o0; c1 = o1;
                __sincosf((float)(r1 & (T_SEQ - 1)) * fr, &sa, &ca);
                o0 = c2 * ca - c3 * sa;
                o1 = c2 * sa + c3 * ca;
                c2 = o0; c3 = o1;
            }
            C[(size_t)r0 * D_MODEL + col]     = c0;
            C[(size_t)r0 * D_MODEL + col + 1] = c1;
            C[(size_t)r1 * D_MODEL + col]     = c2;
            C[(size_t)r1 * D_MODEL + col + 1] = c3;
        }
    }
}

__global__ void __launch_bounds__(256)
qkv_gemm_kernel(const float* __restrict__ x,
                const float* __restrict__ Wq, const float* __restrict__ bq,
                const float* __restrict__ Wk, const float* __restrict__ bk,
                const float* __restrict__ Wv, const float* __restrict__ bv)
{
    int z = blockIdx.z;
    const float* W    = (z == 0) ? Wq : (z == 1) ? Wk : Wv;
    const float* bias = (z == 0) ? bq : (z == 1) ? bk : bv;
    float* C          = (z == 0) ? g_Q : (z == 1) ? g_K : g_V;
    gemm_tf32_core(x, W, bias, C, z < 2);
}

__global__ void __launch_bounds__(256)
out_gemm_kernel(const float* __restrict__ Wo, const float* __restrict__ bo,
                float* __restrict__ out)
{
    gemm_tf32_core(g_O, Wo, bo, out, false);
}

// ---------------------------------------------------------------------------
// Flash attention with tf32 mma.
// Block: 128 queries, 8 warps (16 rows each), 64-key tiles, online softmax.
// smem: QP [64][136] (Q staging, then P), Ks [d][key] [64][72], Vs [key][d] [64][72]
// ---------------------------------------------------------------------------
#define QPP 136
#define KVP 72
#define ATT_SMEM ((64 * QPP + 2 * 64 * KVP) * 4)

__global__ void __launch_bounds__(256)
attn_kernel()
{
    extern __shared__ unsigned sm[];
    unsigned* QP = sm;                  // Q stage / P buffer
    unsigned* Ks = sm + 64 * QPP;
    unsigned* Vs = Ks + 64 * KVP;

    const int tid  = threadIdx.x;
    const int lane = tid & 31;
    const int wid  = tid >> 5;
    const int g = lane >> 2;
    const int t = lane & 3;
    const int m0 = wid * 16;            // warp's query-row base within tile

    const int qt = blockIdx.x;          // 0..15 (128-query tiles)
    const int bh = blockIdx.y;          // 0..63
    const int b = bh >> 4;
    const int h = bh & 15;

    const float* Qg = g_Q + (size_t)(b * T_SEQ + qt * 128) * D_MODEL + h * D_HEAD;
    const float* Kg = g_K + (size_t)(b * T_SEQ) * D_MODEL + h * D_HEAD;
    const float* Vg = g_V + (size_t)(b * T_SEQ) * D_MODEL + h * D_HEAD;

    // Stage Q tile transposed [d][m]
    {
        const int r  = tid >> 1;            // 0..127
        const int d0 = (tid & 1) * 32;
        const float* src = Qg + (size_t)r * D_MODEL + d0;
#pragma unroll
        for (int u = 0; u < 32; u += 4) {
            float4 v = *(const float4*)(src + u);
            QP[(d0 + u + 0) * QPP + r] = f2tf(v.x);
            QP[(d0 + u + 1) * QPP + r] = f2tf(v.y);
            QP[(d0 + u + 2) * QPP + r] = f2tf(v.z);
            QP[(d0 + u + 3) * QPP + r] = f2tf(v.w);
        }
    }
    __syncthreads();

    // Preload Q A-fragments (k = Dh = 64 -> 8 k-frags)
    unsigned qa[8][4];
#pragma unroll
    for (int kf = 0; kf < 8; kf++) {
        const int kr = kf * 8 + t;
        qa[kf][0] = QP[kr * QPP + m0 + g];
        qa[kf][1] = QP[kr * QPP + m0 + g + 8];
        qa[kf][2] = QP[(kr + 4) * QPP + m0 + g];
        qa[kf][3] = QP[(kr + 4) * QPP + m0 + g + 8];
    }

    float o[8][4];
#pragma unroll
    for (int df = 0; df < 8; df++)
#pragma unroll
        for (int i = 0; i < 4; i++) o[df][i] = 0.f;
    float mr0 = -1e30f, mr1 = -1e30f, l0 = 0.f, l1 = 0.f;

    for (int kt = 0; kt < T_SEQ / 64; kt++) {
        __syncthreads();   // prior-iteration Ks/Vs reads done (also covers Q stage on iter 0)
        // Load K (transposed [d][key]) and V ([key][d]) tiles
        {
            const int r  = tid >> 2;           // key 0..63
            const int d0 = (tid & 3) * 16;
            const float* kp = Kg + (size_t)(kt * 64 + r) * D_MODEL + d0;
            const float* vp = Vg + (size_t)(kt * 64 + r) * D_MODEL + d0;
#pragma unroll
            for (int u = 0; u < 16; u += 4) {
                float4 kv = *(const float4*)(kp + u);
                Ks[(d0 + u + 0) * KVP + r] = f2tf(kv.x);
                Ks[(d0 + u + 1) * KVP + r] = f2tf(kv.y);
                Ks[(d0 + u + 2) * KVP + r] = f2tf(kv.z);
                Ks[(d0 + u + 3) * KVP + r] = f2tf(kv.w);
                float4 vv = *(const float4*)(vp + u);
                Vs[r * KVP + d0 + u + 0] = f2tf(vv.x);
                Vs[r * KVP + d0 + u + 1] = f2tf(vv.y);
                Vs[r * KVP + d0 + u + 2] = f2tf(vv.z);
                Vs[r * KVP + d0 + u + 3] = f2tf(vv.w);
            }
        }
        __syncthreads();

        // S = Q K^T (warp: 16 rows x 64 keys)
        float s[8][4];
#pragma unroll
        for (int nf = 0; nf < 8; nf++)
#pragma unroll
            for (int i = 0; i < 4; i++) s[nf][i] = 0.f;
#pragma unroll
        for (int kf = 0; kf < 8; kf++) {
            const int kr = kf * 8 + t;
            unsigned bb[8][2];
#pragma unroll
            for (int nf = 0; nf < 8; nf++) {
                bb[nf][0] = Ks[kr * KVP + nf * 8 + g];
                bb[nf][1] = Ks[(kr + 4) * KVP + nf * 8 + g];
            }
#pragma unroll
            for (int nf = 0; nf < 8; nf++)
                mma_tf32(s[nf], qa[kf], bb[nf]);
        }
#pragma unroll
        for (int nf = 0; nf < 8; nf++)
#pragma unroll
            for (int i = 0; i < 4; i++) s[nf][i] *= 0.125f;

        // Online softmax: thread owns rows g (c0,c1) and g+8 (c2,c3)
        float mx0 = -1e30f, mx1 = -1e30f;
#pragma unroll
        for (int nf = 0; nf < 8; nf++) {
            mx0 = fmaxf(mx0, fmaxf(s[nf][0], s[nf][1]));
            mx1 = fmaxf(mx1, fmaxf(s[nf][2], s[nf][3]));
        }
        mx0 = fmaxf(mx0, __shfl_xor_sync(0xffffffffu, mx0, 1));
        mx0 = fmaxf(mx0, __shfl_xor_sync(0xffffffffu, mx0, 2));
        mx1 = fmaxf(mx1, __shfl_xor_sync(0xffffffffu, mx1, 1));
        mx1 = fmaxf(mx1, __shfl_xor_sync(0xffffffffu, mx1, 2));
        const float mn0 = fmaxf(mr0, mx0);
        const float mn1 = fmaxf(mr1, mx1);
        const float cor0 = __expf(mr0 - mn0);
        const float cor1 = __expf(mr1 - mn1);
        mr0 = mn0; mr1 = mn1;
        float sum0 = 0.f, sum1 = 0.f;
#pragma unroll
        for (int nf = 0; nf < 8; nf++) {
            s[nf][0] = __expf(s[nf][0] - mn0);
            s[nf][1] = __expf(s[nf][1] - mn0);
            s[nf][2] = __expf(s[nf][2] - mn1);
            s[nf][3] = __expf(s[nf][3] - mn1);
            sum0 += s[nf][0] + s[nf][1];
            sum1 += s[nf][2] + s[nf][3];
        }
        sum0 += __shfl_xor_sync(0xffffffffu, sum0, 1);
        sum0 += __shfl_xor_sync(0xffffffffu, sum0, 2);
        sum1 += __shfl_xor_sync(0xffffffffu, sum1, 1);
        sum1 += __shfl_xor_sync(0xffffffffu, sum1, 2);
        l0 = l0 * cor0 + sum0;
        l1 = l1 * cor1 + sum1;
#pragma unroll
        for (int df = 0; df < 8; df++) {
            o[df][0] *= cor0; o[df][1] *= cor0;
            o[df][2] *= cor1; o[df][3] *= cor1;
        }

        // P -> smem (per-warp columns, [key][m] pitch QPP)
#pragma unroll
        for (int nf = 0; nf < 8; nf++) {
            const int k0 = nf * 8 + 2 * t;
            QP[k0 * QPP + m0 + g]           = f2tf(s[nf][0]);
            QP[(k0 + 1) * QPP + m0 + g]     = f2tf(s[nf][1]);
            QP[k0 * QPP + m0 + g + 8]       = f2tf(s[nf][2]);
            QP[(k0 + 1) * QPP + m0 + g + 8] = f2tf(s[nf][3]);
        }
        __syncwarp();

        // O += P V
#pragma unroll
        for (int kf = 0; kf < 8; kf++) {
            const int kr = kf * 8 + t;
            unsigned pa[4];
            pa[0] = QP[kr * QPP + m0 + g];
            pa[1] = QP[kr * QPP + m0 + g + 8];
            pa[2] = QP[(kr + 4) * QPP + m0 + g];
            pa[3] = QP[(kr + 4) * QPP + m0 + g + 8];
            unsigned bv[8][2];
#pragma unroll
            for (int df = 0; df < 8; df++) {
                bv[df][0] = Vs[kr * KVP + df * 8 + g];
                bv[df][1] = Vs[(kr + 4) * KVP + df * 8 + g];
            }
#pragma unroll
            for (int df = 0; df < 8; df++)
                mma_tf32(o[df], pa, bv[df]);
        }
        __syncwarp();   // P buffer reads done before next-iter writes
    }

    // Finalize, write O [B*T][H*Dh]
    const float inv0 = 1.f / l0;
    const float inv1 = 1.f / l1;
    const int r0 = b * T_SEQ + qt * 128 + m0 + g;
    const int r1 = r0 + 8;
#pragma unroll
    for (int df = 0; df < 8; df++) {
        const int col = h * D_HEAD + df * 8 + 2 * t;
        g_O[(size_t)r0 * D_MODEL + col]     = o[df][0] * inv0;
        g_O[(size_t)r0 * D_MODEL + col + 1] = o[df][1] * inv0;
        g_O[(size_t)r1 * D_MODEL + col]     = o[df][2] * inv1;
        g_O[(size_t)r1 * D_MODEL + col + 1] = o[df][3] * inv1;
    }
}

// ---------------------------------------------------------------------------
extern "C" void kernel_launch(void* const* d_in, const int* in_sizes, int n_in,
                              void* d_out, int out_size)
{
    const float* x  = (const float*)d_in[0];
    const float* Wq = (const float*)d_in[1];
    const float* bq = (const float*)d_in[2];
    const float* Wk = (const float*)d_in[3];
    const float* bk = (const float*)d_in[4];
    const float* Wv = (const float*)d_in[5];
    const float* bv = (const float*)d_in[6];
    const float* Wo = (const float*)d_in[7];
    const float* bo = (const float*)d_in[8];
    float* out = (float*)d_out;

    static bool attr_set = false;
    if (!attr_set) {
        cudaFuncSetAttribute(attn_kernel,
                             cudaFuncAttributeMaxDynamicSharedMemorySize,
                             ATT_SMEM);
        attr_set = true;
    }

    dim3 gq(D_MODEL / 128, BT / 128, 3);
    qkv_gemm_kernel<<<gq, 256>>>(x, Wq, bq, Wk, bk, Wv, bv);

    dim3 ga(T_SEQ / 128, BATCH * NHEAD);
    attn_kernel<<<ga, 256, ATT_SMEM>>>();

    dim3 go(D_MODEL / 128, BT / 128, 1);
    out_gemm_kernel<<<go, 256>>>(Wo, bo, out);
}

// round 4
// speedup vs baseline: 4.1429x; 1.5600x over previous
#include <cuda_runtime.h>
#include <math.h>
#include <stdint.h>

#define D_MODEL 1024
#define NHEAD   16
#define D_HEAD  64
#define BATCH   4
#define T_SEQ   2048
#define BT      (BATCH * T_SEQ)   // 8192

__device__ float g_Q[BT * D_MODEL];
__device__ float g_K[BT * D_MODEL];
__device__ float g_V[BT * D_MODEL];     // TRANSPOSED layout: [D_MODEL][BT]
__device__ float g_X[BT * D_MODEL];     // rounded x, later attention output (rounded)
__device__ float g_W[4 * D_MODEL * D_MODEL];   // rounded Wq,Wk,Wv,Wo

// ---------------------------------------------------------------------------
// helpers
// ---------------------------------------------------------------------------
__device__ __forceinline__ unsigned f2tf(float f) {
    unsigned u;
    asm("cvt.rna.tf32.f32 %0, %1;" : "=r"(u) : "f"(f));
    return u;
}

__device__ __forceinline__ void mma8(float* c, const unsigned* a, const unsigned* b) {
    asm volatile(
        "mma.sync.aligned.m16n8k8.row.col.f32.tf32.tf32.f32 "
        "{%0,%1,%2,%3}, {%4,%5,%6,%7}, {%8,%9}, {%0,%1,%2,%3};"
        : "+f"(c[0]), "+f"(c[1]), "+f"(c[2]), "+f"(c[3])
        : "r"(a[0]), "r"(a[1]), "r"(a[2]), "r"(a[3]), "r"(b[0]), "r"(b[1]));
}

__device__ __forceinline__ void cp16(uint32_t s, const void* g) {
    asm volatile("cp.async.cg.shared.global [%0], [%1], 16;" :: "r"(s), "l"(g));
}
__device__ __forceinline__ void cpcommit() {
    asm volatile("cp.async.commit_group;" ::: "memory");
}
template <int N>
__device__ __forceinline__ void cpwait() {
    asm volatile("cp.async.wait_group %0;" :: "n"(N) : "memory");
}

// ---------------------------------------------------------------------------
// tf32 mma.sync GEMM: C[M,N] = A[M,K] @ W[N,K]^T + bias
// CTA 128x256, BK=32, 8 warps at 64x64, 3-stage cp.async pipeline.
// MODE: 0 = plain store (final out), 1 = RoPE + tf32-round (Q/K),
//       2 = tf32-round + transposed store (V -> [feature][token])
// ---------------------------------------------------------------------------
#define GBM 128
#define GBN 256
#define GBK 32
#define GPA 36                               // smem row pitch (words), BK+4
#define GSTAGE ((GBM + GBN) * GPA * 4)       // 55296 B
#define GSMEM  (3 * GSTAGE)                  // 165888 B

template <int MODE>
__global__ void __launch_bounds__(256)
gemm_k(const float* __restrict__ A, const float* __restrict__ W,
       const float* __restrict__ bias, float* __restrict__ C)
{
    extern __shared__ char smem[];
    const int tid = threadIdx.x, lane = tid & 31, wid = tid >> 5;
    const int g = lane >> 2, t = lane & 3;
    const int wm = (wid & 1) * 64, wn = (wid >> 1) * 64;
    const int bm = blockIdx.y * GBM, bn = blockIdx.x * GBN;
    const uint32_t sb = (uint32_t)__cvta_generic_to_shared(smem);

    float acc[4][8][4];
#pragma unroll
    for (int mf = 0; mf < 4; mf++)
#pragma unroll
        for (int nf = 0; nf < 8; nf++)
#pragma unroll
            for (int i = 0; i < 4; i++) acc[mf][nf][i] = 0.f;

    auto load_stage = [&](int kt, int s) {
        const uint32_t as = sb + s * GSTAGE;
        const uint32_t bs = as + GBM * GPA * 4;
        const float* Ab = A + (size_t)bm * D_MODEL + kt * GBK;
        const float* Wb = W + (size_t)bn * D_MODEL + kt * GBK;
#pragma unroll
        for (int u = 0; u < 4; u++) {
            const int idx = tid + 256 * u, r = idx >> 3, c = idx & 7;
            cp16(as + (r * GPA + c * 4) * 4, Ab + (size_t)r * D_MODEL + c * 4);
        }
#pragma unroll
        for (int u = 0; u < 8; u++) {
            const int idx = tid + 256 * u, r = idx >> 3, c = idx & 7;
            cp16(bs + (r * GPA + c * 4) * 4, Wb + (size_t)r * D_MODEL + c * 4);
        }
    };

    load_stage(0, 0); cpcommit();
    load_stage(1, 1); cpcommit();

    const int NCH = D_MODEL / GBK;   // 32
    for (int kt = 0; kt < NCH; kt++) {
        if (kt + 2 < NCH) load_stage(kt + 2, (kt + 2) % 3);
        cpcommit();
        cpwait<1>();
        __syncthreads();
        const unsigned* Au = (const unsigned*)(smem + (kt % 3) * GSTAGE);
        const unsigned* Bu = Au + GBM * GPA;
#pragma unroll
        for (int kf = 0; kf < 4; kf++) {
            const int k0 = kf * 8 + t;
            unsigned a[4][4], b[8][2];
#pragma unroll
            for (int mf = 0; mf < 4; mf++) {
                const int mr = wm + mf * 16 + g;
                a[mf][0] = Au[mr * GPA + k0];
                a[mf][1] = Au[(mr + 8) * GPA + k0];
                a[mf][2] = Au[mr * GPA + k0 + 4];
                a[mf][3] = Au[(mr + 8) * GPA + k0 + 4];
            }
#pragma unroll
            for (int nf = 0; nf < 8; nf++) {
                const int nr = wn + nf * 8 + g;
                b[nf][0] = Bu[nr * GPA + k0];
                b[nf][1] = Bu[nr * GPA + k0 + 4];
            }
#pragma unroll
            for (int mf = 0; mf < 4; mf++)
#pragma unroll
                for (int nf = 0; nf < 8; nf++) mma8(acc[mf][nf], a[mf], b[nf]);
        }
        __syncthreads();
    }
    cpwait<0>();
    __syncthreads();

    if (MODE == 2) {
        // V: bias + round, smem transpose (pitch 261, odd -> conflict-free cols),
        // write transposed gmem [feature][token]
        float* S = (float*)smem;
#pragma unroll
        for (int mf = 0; mf < 4; mf++) {
            const int lr = wm + mf * 16 + g;
#pragma unroll
            for (int nf = 0; nf < 8; nf++) {
                const int lc = wn + nf * 8 + 2 * t;
                const float b0 = bias[bn + lc], b1 = bias[bn + lc + 1];
                S[lr * 261 + lc]           = __uint_as_float(f2tf(acc[mf][nf][0] + b0));
                S[lr * 261 + lc + 1]       = __uint_as_float(f2tf(acc[mf][nf][1] + b1));
                S[(lr + 8) * 261 + lc]     = __uint_as_float(f2tf(acc[mf][nf][2] + b0));
                S[(lr + 8) * 261 + lc + 1] = __uint_as_float(f2tf(acc[mf][nf][3] + b1));
            }
        }
        __syncthreads();
        for (int task = wid; task < 1024; task += 8) {
            const int f = task & 255, ch = task >> 8;
            const int tok = ch * 32 + lane;
            C[(size_t)(bn + f) * BT + bm + tok] = S[tok * 261 + f];
        }
    } else {
#pragma unroll
        for (int mf = 0; mf < 4; mf++) {
            const int r0 = bm + wm + mf * 16 + g, r1 = r0 + 8;
#pragma unroll
            for (int nf = 0; nf < 8; nf++) {
                const int col = bn + wn + nf * 8 + 2 * t;
                const float b0 = bias[col], b1 = bias[col + 1];
                float v0 = acc[mf][nf][0] + b0, v1 = acc[mf][nf][1] + b1;
                float v2 = acc[mf][nf][2] + b0, v3 = acc[mf][nf][3] + b1;
                if (MODE == 1) {
                    const float fr = (float)((col & (D_HEAD - 1)) >> 1) * 1e-4f;
                    float sa, ca;
                    __sincosf((float)(r0 & (T_SEQ - 1)) * fr, &sa, &ca);
                    const float w0 = v0 * ca - v1 * sa, w1 = v0 * sa + v1 * ca;
                    __sincosf((float)(r1 & (T_SEQ - 1)) * fr, &sa, &ca);
                    const float w2 = v2 * ca - v3 * sa, w3 = v2 * sa + v3 * ca;
                    v0 = __uint_as_float(f2tf(w0)); v1 = __uint_as_float(f2tf(w1));
                    v2 = __uint_as_float(f2tf(w2)); v3 = __uint_as_float(f2tf(w3));
                }
                *(float2*)&C[(size_t)r0 * D_MODEL + col] = make_float2(v0, v1);
                *(float2*)&C[(size_t)r1 * D_MODEL + col] = make_float2(v2, v3);
            }
        }
    }
}

// ---------------------------------------------------------------------------
// Pre-pass: RNA-round x -> g_X, weights -> g_W
// ---------------------------------------------------------------------------
__global__ void __launch_bounds__(256)
round_pass(const float4* __restrict__ x, const float4* __restrict__ wq,
           const float4* __restrict__ wk, const float4* __restrict__ wv,
           const float4* __restrict__ wo)
{
    const int NX = BT * D_MODEL / 4;
    const int NW = D_MODEL * D_MODEL / 4;
    float4* gx = (float4*)g_X;
    float4* gw = (float4*)g_W;
    for (int i = blockIdx.x * blockDim.x + threadIdx.x; i < NX + 4 * NW;
         i += gridDim.x * blockDim.x) {
        const float4* src;
        float4* dst;
        if (i < NX) { src = x + i; dst = gx + i; }
        else {
            const int j = i - NX, w = j / NW, k = j - w * NW;
            const float4* s4 = (w == 0) ? wq : (w == 1) ? wk : (w == 2) ? wv : wo;
            src = s4 + k; dst = gw + j;
        }
        float4 v = *src;
        v.x = __uint_as_float(f2tf(v.x));
        v.y = __uint_as_float(f2tf(v.y));
        v.z = __uint_as_float(f2tf(v.z));
        v.w = __uint_as_float(f2tf(v.w));
        *dst = v;
    }
}

// ---------------------------------------------------------------------------
// Flash attention, tf32 mma.sync.
// 128 queries/CTA, 4 warps x 32 rows, 64-key tiles, cp.async double-buffered
// K/V, Q fragments in registers (pre-scaled 1/8), P via in-register shfl
// transpose (no smem roundtrip).
// smem (floats): Q[128][68] | K0[64][68] | K1 | V0[64][68] (layout [d][key]) | V1
// ---------------------------------------------------------------------------
#define AQ  0
#define AK0 (128 * 68)
#define AK1 (AK0 + 64 * 68)
#define AV0 (AK1 + 64 * 68)
#define AV1 (AV0 + 64 * 68)
#define ATT_SMEM ((AV1 + 64 * 68) * 4)   // 104448 B

__global__ void __launch_bounds__(128)
attn_kernel()
{
    extern __shared__ float sm[];
    const uint32_t sb = (uint32_t)__cvta_generic_to_shared(sm);
    const int tid = threadIdx.x, lane = tid & 31, wid = tid >> 5;
    const int g = lane >> 2, t = lane & 3;
    const int m0 = wid * 32;
    const int qt = blockIdx.x, bh = blockIdx.y;
    const int b = bh >> 4, h = bh & 15;

    const float* Qg = g_Q + (size_t)(b * T_SEQ + qt * 128) * D_MODEL + h * D_HEAD;
    const float* Kg = g_K + (size_t)(b * T_SEQ) * D_MODEL + h * D_HEAD;
    const float* Vg = g_V + (size_t)(h * D_HEAD) * BT + b * T_SEQ;   // [d][token]

    auto load_kv = [&](int kt, int buf) {
        const float* kp = Kg + (size_t)(kt * 64) * D_MODEL;
        const float* vp = Vg + kt * 64;
        const int kb = buf ? AK1 : AK0, vb = buf ? AV1 : AV0;
#pragma unroll
        for (int u = 0; u < 8; u++) {
            const int idx = tid + 128 * u, r = idx >> 4, c = idx & 15;
            cp16(sb + (kb + r * 68 + c * 4) * 4, kp + (size_t)r * D_MODEL + c * 4);
        }
#pragma unroll
        for (int u = 0; u < 8; u++) {
            const int idx = tid + 128 * u, r = idx >> 4, c = idx & 15;
            cp16(sb + (vb + r * 68 + c * 4) * 4, vp + (size_t)r * BT + c * 4);
        }
    };

    // stage Q, then KV0
#pragma unroll
    for (int u = 0; u < 16; u++) {
        const int idx = tid + 128 * u, r = idx >> 4, c = idx & 15;
        cp16(sb + (AQ + r * 68 + c * 4) * 4, Qg + (size_t)r * D_MODEL + c * 4);
    }
    cpcommit();
    load_kv(0, 0);
    cpcommit();
    cpwait<1>();     // Q complete (KV0 may be in flight)
    __syncthreads();

    // Q A-fragments, pre-scaled by 1/sqrt(Dh)=0.125 (exact in tf32)
    unsigned qa[2][8][4];
#pragma unroll
    for (int mf = 0; mf < 2; mf++)
#pragma unroll
        for (int kf = 0; kf < 8; kf++) {
            const int mr = m0 + mf * 16 + g, k0 = kf * 8 + t;
            qa[mf][kf][0] = __float_as_uint(sm[AQ + mr * 68 + k0] * 0.125f);
            qa[mf][kf][1] = __float_as_uint(sm[AQ + (mr + 8) * 68 + k0] * 0.125f);
            qa[mf][kf][2] = __float_as_uint(sm[AQ + mr * 68 + k0 + 4] * 0.125f);
            qa[mf][kf][3] = __float_as_uint(sm[AQ + (mr + 8) * 68 + k0 + 4] * 0.125f);
        }

    float o[2][8][4];
#pragma unroll
    for (int mf = 0; mf < 2; mf++)
#pragma unroll
        for (int df = 0; df < 8; df++)
#pragma unroll
            for (int i = 0; i < 4; i++) o[mf][df][i] = 0.f;
    float mrun[2][2] = {{-1e30f, -1e30f}, {-1e30f, -1e30f}};
    float lrun[2][2] = {{0.f, 0.f}, {0.f, 0.f}};

    const int srcA = (lane & ~3) | (t >> 1);

    for (int kt = 0; kt < T_SEQ / 64; kt++) {
        __syncthreads();                       // prior compute done -> buffers free
        if (kt + 1 < T_SEQ / 64) load_kv(kt + 1, (kt + 1) & 1);
        cpcommit();
        cpwait<1>();                           // KV(kt) ready
        __syncthreads();
        const unsigned* Ku = (const unsigned*)(sm + ((kt & 1) ? AK1 : AK0));
        const unsigned* Vu = (const unsigned*)(sm + ((kt & 1) ? AV1 : AV0));

        // S = (Q/8) K^T
        float s[2][8][4];
#pragma unroll
        for (int mf = 0; mf < 2; mf++)
#pragma unroll
            for (int nf = 0; nf < 8; nf++)
#pragma unroll
                for (int i = 0; i < 4; i++) s[mf][nf][i] = 0.f;
#pragma unroll
        for (int kf = 0; kf < 8; kf++) {
            const int k0 = kf * 8 + t;
            unsigned kb[8][2];
#pragma unroll
            for (int nf = 0; nf < 8; nf++) {
                kb[nf][0] = Ku[(nf * 8 + g) * 68 + k0];
                kb[nf][1] = Ku[(nf * 8 + g) * 68 + k0 + 4];
            }
#pragma unroll
            for (int mf = 0; mf < 2; mf++)
#pragma unroll
                for (int nf = 0; nf < 8; nf++) mma8(s[mf][nf], qa[mf][kf], kb[nf]);
        }

        // online softmax (4 row-states/thread)
#pragma unroll
        for (int mf = 0; mf < 2; mf++) {
            float mx0 = -1e30f, mx1 = -1e30f;
#pragma unroll
            for (int nf = 0; nf < 8; nf++) {
                mx0 = fmaxf(mx0, fmaxf(s[mf][nf][0], s[mf][nf][1]));
                mx1 = fmaxf(mx1, fmaxf(s[mf][nf][2], s[mf][nf][3]));
            }
            mx0 = fmaxf(mx0, __shfl_xor_sync(0xffffffffu, mx0, 1));
            mx0 = fmaxf(mx0, __shfl_xor_sync(0xffffffffu, mx0, 2));
            mx1 = fmaxf(mx1, __shfl_xor_sync(0xffffffffu, mx1, 1));
            mx1 = fmaxf(mx1, __shfl_xor_sync(0xffffffffu, mx1, 2));
            const float nm0 = fmaxf(mrun[mf][0], mx0);
            const float nm1 = fmaxf(mrun[mf][1], mx1);
            const float c0 = __expf(mrun[mf][0] - nm0);
            const float c1 = __expf(mrun[mf][1] - nm1);
            mrun[mf][0] = nm0; mrun[mf][1] = nm1;
            float su0 = 0.f, su1 = 0.f;
#pragma unroll
            for (int nf = 0; nf < 8; nf++) {
                s[mf][nf][0] = __expf(s[mf][nf][0] - nm0);
                s[mf][nf][1] = __expf(s[mf][nf][1] - nm0);
                s[mf][nf][2] = __expf(s[mf][nf][2] - nm1);
                s[mf][nf][3] = __expf(s[mf][nf][3] - nm1);
                su0 += s[mf][nf][0] + s[mf][nf][1];
                su1 += s[mf][nf][2] + s[mf][nf][3];
            }
            su0 += __shfl_xor_sync(0xffffffffu, su0, 1);
            su0 += __shfl_xor_sync(0xffffffffu, su0, 2);
            su1 += __shfl_xor_sync(0xffffffffu, su1, 1);
            su1 += __shfl_xor_sync(0xffffffffu, su1, 2);
            lrun[mf][0] = lrun[mf][0] * c0 + su0;
            lrun[mf][1] = lrun[mf][1] * c1 + su1;
#pragma unroll
            for (int df = 0; df < 8; df++) {
                o[mf][df][0] *= c0; o[mf][df][1] *= c0;
                o[mf][df][2] *= c1; o[mf][df][3] *= c1;
            }
            // round P to tf32 in place (bits carried in float regs)
#pragma unroll
            for (int nf = 0; nf < 8; nf++)
#pragma unroll
                for (int i = 0; i < 4; i++)
                    s[mf][nf][i] = __uint_as_float(f2tf(s[mf][nf][i]));
        }

        // O += P V  (P C-frag -> A-frag via quad shuffles)
#pragma unroll
        for (int kf = 0; kf < 8; kf++) {
            const int k0 = kf * 8 + t;
            unsigned vb[8][2];
#pragma unroll
            for (int df = 0; df < 8; df++) {
                vb[df][0] = Vu[(df * 8 + g) * 68 + k0];
                vb[df][1] = Vu[(df * 8 + g) * 68 + k0 + 4];
            }
#pragma unroll
            for (int mf = 0; mf < 2; mf++) {
                unsigned pa[4];
                float e, od;
                e  = __shfl_sync(0xffffffffu, s[mf][kf][0], srcA);
                od = __shfl_sync(0xffffffffu, s[mf][kf][1], srcA);
                pa[0] = __float_as_uint((t & 1) ? od : e);
                e  = __shfl_sync(0xffffffffu, s[mf][kf][2], srcA);
                od = __shfl_sync(0xffffffffu, s[mf][kf][3], srcA);
                pa[1] = __float_as_uint((t & 1) ? od : e);
                e  = __shfl_sync(0xffffffffu, s[mf][kf][0], srcA + 2);
                od = __shfl_sync(0xffffffffu, s[mf][kf][1], srcA + 2);
                pa[2] = __float_as_uint((t & 1) ? od : e);
                e  = __shfl_sync(0xffffffffu, s[mf][kf][2], srcA + 2);
                od = __shfl_sync(0xffffffffu, s[mf][kf][3], srcA + 2);
                pa[3] = __float_as_uint((t & 1) ? od : e);
#pragma unroll
                for (int df = 0; df < 8; df++) mma8(o[mf][df], pa, vb[df]);
            }
        }
    }

    // finalize (rounded for the tf32 out-GEMM)
#pragma unroll
    for (int mf = 0; mf < 2; mf++) {
        const float inv0 = 1.f / lrun[mf][0];
        const float inv1 = 1.f / lrun[mf][1];
        const int r0 = b * T_SEQ + qt * 128 + m0 + mf * 16 + g, r1 = r0 + 8;
#pragma unroll
        for (int df = 0; df < 8; df++) {
            const int col = h * D_HEAD + df * 8 + 2 * t;
            *(float2*)&g_X[(size_t)r0 * D_MODEL + col] = make_float2(
                __uint_as_float(f2tf(o[mf][df][0] * inv0)),
                __uint_as_float(f2tf(o[mf][df][1] * inv0)));
            *(float2*)&g_X[(size_t)r1 * D_MODEL + col] = make_float2(
                __uint_as_float(f2tf(o[mf][df][2] * inv1)),
                __uint_as_float(f2tf(o[mf][df][3] * inv1)));
        }
    }
}

// ---------------------------------------------------------------------------
extern "C" void kernel_launch(void* const* d_in, const int* in_sizes, int n_in,
                              void* d_out, int out_size)
{
    const float* x  = (const float*)d_in[0];
    const float* bq = (const float*)d_in[2];
    const float* bk = (const float*)d_in[4];
    const float* bv = (const float*)d_in[6];
    const float* bo = (const float*)d_in[8];
    float* out = (float*)d_out;

    static bool attr_set = false;
    if (!attr_set) {
        cudaFuncSetAttribute(gemm_k<0>, cudaFuncAttributeMaxDynamicSharedMemorySize, GSMEM);
        cudaFuncSetAttribute(gemm_k<1>, cudaFuncAttributeMaxDynamicSharedMemorySize, GSMEM);
        cudaFuncSetAttribute(gemm_k<2>, cudaFuncAttributeMaxDynamicSharedMemorySize, GSMEM);
        cudaFuncSetAttribute(attn_kernel, cudaFuncAttributeMaxDynamicSharedMemorySize, ATT_SMEM);
        attr_set = true;
    }

    float* gW;  cudaGetSymbolAddress((void**)&gW, g_W);
    float* gX;  cudaGetSymbolAddress((void**)&gX, g_X);
    float* gQ;  cudaGetSymbolAddress((void**)&gQ, g_Q);
    float* gK;  cudaGetSymbolAddress((void**)&gK, g_K);
    float* gV;  cudaGetSymbolAddress((void**)&gV, g_V);

    round_pass<<<1024, 256>>>((const float4*)x, (const float4*)d_in[1],
                              (const float4*)d_in[3], (const float4*)d_in[5],
                              (const float4*)d_in[7]);

    const size_t WSZ = (size_t)D_MODEL * D_MODEL;
    dim3 gg(D_MODEL / GBN, BT / GBM);
    gemm_k<1><<<gg, 256, GSMEM>>>(gX, gW,           bq, gQ);
    gemm_k<1><<<gg, 256, GSMEM>>>(gX, gW + WSZ,     bk, gK);
    gemm_k<2><<<gg, 256, GSMEM>>>(gX, gW + 2 * WSZ, bv, gV);

    dim3 ga(T_SEQ / 128, BATCH * NHEAD);
    attn_kernel<<<ga, 128, ATT_SMEM>>>();

    gemm_k<0><<<gg, 256, GSMEM>>>(gX, gW + 3 * WSZ, bo, out);
}